// round 5
// baseline (speedup 1.0000x reference)
#include <cuda_runtime.h>
#include <cuda_bf16.h>

#define NPTS 4096
#define NF   (NPTS - 2)
#define EPSF 1e-8f
#define LT   256
#define PT_CHUNK 1024
#define NBLK ((NPTS / 4) * (NPTS / PT_CHUNK))   // 1024 frame-groups x 4 point-chunks = 4096

typedef unsigned long long u64;

// Scratch (device globals only — allocations forbidden)
// Point data, SoA rows: 0..2 = -pred.{x,y,z}, 3..5 = true.{x,y,z}
__device__ __align__(16) float g_pts[6][NPTS];
// Fused frame constants, SoA over frames (padded to 4096):
// k=0..8: M = Rp^T * Rt (row-major), k=9..11: c = op - M*ot
__device__ __align__(16) float g_fc[12][NPTS];
__device__ double g_acc;
__device__ unsigned g_tick;

__device__ __forceinline__ float rsqrt_fast(float x) {
    float y; asm("rsqrt.approx.f32 %0, %1;" : "=f"(y) : "f"(x)); return y;
}
__device__ __forceinline__ float sqrt_fast(float x) {
    float y; asm("sqrt.approx.f32 %0, %1;" : "=f"(y) : "f"(x)); return y;
}
__device__ __forceinline__ u64 dupf(float a) {
    u64 r; asm("mov.b64 %0, {%1, %1};" : "=l"(r) : "f"(a)); return r;
}
__device__ __forceinline__ u64 ffma2(u64 a, u64 b, u64 c) {
    u64 d; asm("fma.rn.f32x2 %0, %1, %2, %3;" : "=l"(d) : "l"(a), "l"(b), "l"(c));
    return d;
}
__device__ __forceinline__ u64 fadd2(u64 a, u64 b) {
    u64 d; asm("add.rn.f32x2 %0, %1, %2;" : "=l"(d) : "l"(a), "l"(b));
    return d;
}
__device__ __forceinline__ void unpk(u64 v, float& lo, float& hi) {
    asm("mov.b64 {%0, %1}, %2;" : "=f"(lo), "=f"(hi) : "l"(v));
}

__device__ __forceinline__ void build_frame(const float* __restrict__ c, int i,
                                            float* __restrict__ R, float* __restrict__ o) {
    float ox = c[3*i+3], oy = c[3*i+4], oz = c[3*i+5];
    float ax = c[3*i+6] - ox, ay = c[3*i+7] - oy, az = c[3*i+8] - oz;
    float i1 = rsqrt_fast(ax*ax + ay*ay + az*az);
    ax *= i1; ay *= i1; az *= i1;
    float bx = c[3*i] - ox, by = c[3*i+1] - oy, bz = c[3*i+2] - oz;
    float d = bx*ax + by*ay + bz*az;
    bx -= d*ax; by -= d*ay; bz -= d*az;
    float i2 = rsqrt_fast(bx*bx + by*by + bz*bz);
    bx *= i2; by *= i2; bz *= i2;
    R[0]=ax; R[1]=ay; R[2]=az;
    R[3]=bx; R[4]=by; R[5]=bz;
    R[6]=ay*bz - az*by; R[7]=az*bx - ax*bz; R[8]=ax*by - ay*bx;
    o[0]=ox; o[1]=oy; o[2]=oz;
}

__global__ void prep_kernel(const float* __restrict__ pred, const float* __restrict__ tru) {
    int i = blockIdx.x * blockDim.x + threadIdx.x;
    if (i == 0) g_acc = 0.0;
    if (i < NPTS) {
        g_pts[0][i] = -pred[3*i];
        g_pts[1][i] = -pred[3*i+1];
        g_pts[2][i] = -pred[3*i+2];
        g_pts[3][i] = tru[3*i];
        g_pts[4][i] = tru[3*i+1];
        g_pts[5][i] = tru[3*i+2];
    }
    if (i < NF) {
        float Rp[9], op[3], Rt[9], ot[3];
        build_frame(pred, i, Rp, op);
        build_frame(tru,  i, Rt, ot);
        float M[9];
        #pragma unroll
        for (int r = 0; r < 3; r++)
            #pragma unroll
            for (int cc = 0; cc < 3; cc++)
                M[3*r+cc] = Rp[r]*Rt[cc] + Rp[3+r]*Rt[3+cc] + Rp[6+r]*Rt[6+cc];
        #pragma unroll
        for (int k = 0; k < 9; k++) g_fc[k][i] = M[k];
        #pragma unroll
        for (int r = 0; r < 3; r++)
            g_fc[9 + r][i] = op[r] - (M[3*r]*ot[0] + M[3*r+1]*ot[1] + M[3*r+2]*ot[2]);
    } else if (i < NPTS) {
        // Pad frames: dist clamps to exactly 10.0; removed analytically at the end.
        #pragma unroll
        for (int k = 0; k < 12; k++) g_fc[k][i] = 0.0f;
        g_fc[9][i] = 1e6f;
    }
}

// Each block: 4 frames (two f32x2 frame-pairs) x 1024 points.
__global__ void __launch_bounds__(LT, 3) loss_kernel(float* __restrict__ out) {
    const int f  = (blockIdx.x >> 2) * 4;
    const int n0 = (blockIdx.x & 3) * PT_CHUNK;

    // Frame constants: single base pointer, immediate row offsets (16KB apart).
    const float* __restrict__ fc = &g_fc[0][f];
    u64 A[12], B[12];
    #pragma unroll
    for (int k = 0; k < 12; k++) {
        A[k] = *(const u64*)(fc + k * NPTS);
        B[k] = *(const u64*)(fc + k * NPTS + 2);
    }
    const u64 eps2 = dupf(EPSF);

    float s0 = 0.0f, s1 = 0.0f, s2 = 0.0f, s3 = 0.0f;

    // Point data: single base pointer, immediate row offsets.
    const float* __restrict__ pt = &g_pts[0][n0 + threadIdx.x];

    #pragma unroll 2
    for (int it = 0; it < PT_CHUNK / LT; it++, pt += LT) {
        u64 NX = dupf(pt[0 * NPTS]);   // -px
        u64 NY = dupf(pt[1 * NPTS]);   // -py
        u64 NZ = dupf(pt[2 * NPTS]);   // -pz
        u64 U  = dupf(pt[3 * NPTS]);   // qx
        u64 V  = dupf(pt[4 * NPTS]);   // qy
        u64 W  = dupf(pt[5 * NPTS]);   // qz

        // d = M*q + c - p   (sign of d irrelevant for |d|^2)
        u64 ax = ffma2(A[0], U, ffma2(A[1], V, ffma2(A[2], W, fadd2(A[9],  NX))));
        u64 ay = ffma2(A[3], U, ffma2(A[4], V, ffma2(A[5], W, fadd2(A[10], NY))));
        u64 az = ffma2(A[6], U, ffma2(A[7], V, ffma2(A[8], W, fadd2(A[11], NZ))));

        u64 bx = ffma2(B[0], U, ffma2(B[1], V, ffma2(B[2], W, fadd2(B[9],  NX))));
        u64 by = ffma2(B[3], U, ffma2(B[4], V, ffma2(B[5], W, fadd2(B[10], NY))));
        u64 bz = ffma2(B[6], U, ffma2(B[7], V, ffma2(B[8], W, fadd2(B[11], NZ))));

        u64 ssa = ffma2(ax, ax, ffma2(ay, ay, ffma2(az, az, eps2)));
        u64 ssb = ffma2(bx, bx, ffma2(by, by, ffma2(bz, bz, eps2)));

        float v0, v1, v2, v3;
        unpk(ssa, v0, v1);
        unpk(ssb, v2, v3);
        s0 += fminf(sqrt_fast(v0), 10.0f);
        s1 += fminf(sqrt_fast(v1), 10.0f);
        s2 += fminf(sqrt_fast(v2), 10.0f);
        s3 += fminf(sqrt_fast(v3), 10.0f);
    }

    float sum = (s0 + s1) + (s2 + s3);
    #pragma unroll
    for (int o = 16; o > 0; o >>= 1)
        sum += __shfl_down_sync(0xffffffffu, sum, o);

    __shared__ float wsum[LT / 32];
    int lane = threadIdx.x & 31;
    int wid  = threadIdx.x >> 5;
    if (lane == 0) wsum[wid] = sum;
    __syncthreads();
    if (threadIdx.x == 0) {
        float v = 0.0f;
        #pragma unroll
        for (int w = 0; w < LT / 32; w++) v += wsum[w];
        atomicAdd(&g_acc, (double)v);
        __threadfence();
        unsigned t = atomicAdd(&g_tick, 1u);
        if (t == (unsigned)(gridDim.x - 1)) {
            double total = *((volatile double*)&g_acc);
            total -= 2.0 * (double)NPTS * 10.0;   // pad frames contribute exactly 10 each
            out[0] = (float)(total / ((double)NF * (double)NPTS) / 10.0);
            g_tick = 0u;  // reset for next graph replay
        }
    }
}

extern "C" void kernel_launch(void* const* d_in, const int* in_sizes, int n_in,
                              void* d_out, int out_size) {
    const float* pred = (const float*)d_in[0];
    const float* tru  = (const float*)d_in[1];
    float* out = (float*)d_out;

    prep_kernel<<<(NPTS + 255) / 256, 256>>>(pred, tru);
    loss_kernel<<<NBLK, LT>>>(out);
}

// round 6
// speedup vs baseline: 1.2503x; 1.2503x over previous
#include <cuda_runtime.h>
#include <cuda_bf16.h>

#define NPTS 4096
#define NF   (NPTS - 2)
#define EPSF 1e-8f
#define LT   256
#define PT_CHUNK 2048
#define NBLK ((NPTS / 4) * (NPTS / PT_CHUNK))   // 1024 frame-groups x 2 chunks = 2048

typedef unsigned long long u64;

// Scratch (device globals only — allocations forbidden)
// Point data pre-duplicated for f32x2: rows 0..2 = (-p,-p).{x,y,z}, 3..5 = (q,q).{x,y,z}
__device__ __align__(16) u64 g_pd[6][NPTS];
// Fused frame constants, SoA over frames (padded to 4096):
// k=0..8: M = Rp^T * Rt (row-major), k=9..11: c = op - M*ot
__device__ __align__(16) float g_fc[12][NPTS];
__device__ double g_acc;
__device__ unsigned g_tick;

__device__ __forceinline__ float rsqrt_fast(float x) {
    float y; asm("rsqrt.approx.f32 %0, %1;" : "=f"(y) : "f"(x)); return y;
}
__device__ __forceinline__ float sqrt_fast(float x) {
    float y; asm("sqrt.approx.f32 %0, %1;" : "=f"(y) : "f"(x)); return y;
}
__device__ __forceinline__ u64 dupf(float a) {
    u64 r; asm("mov.b64 %0, {%1, %1};" : "=l"(r) : "f"(a)); return r;
}
__device__ __forceinline__ u64 ffma2(u64 a, u64 b, u64 c) {
    u64 d; asm("fma.rn.f32x2 %0, %1, %2, %3;" : "=l"(d) : "l"(a), "l"(b), "l"(c));
    return d;
}
__device__ __forceinline__ u64 fadd2(u64 a, u64 b) {
    u64 d; asm("add.rn.f32x2 %0, %1, %2;" : "=l"(d) : "l"(a), "l"(b));
    return d;
}
__device__ __forceinline__ void unpk(u64 v, float& lo, float& hi) {
    asm("mov.b64 {%0, %1}, %2;" : "=f"(lo), "=f"(hi) : "l"(v));
}

__device__ __forceinline__ void build_frame(const float* __restrict__ c, int i,
                                            float* __restrict__ R, float* __restrict__ o) {
    float ox = c[3*i+3], oy = c[3*i+4], oz = c[3*i+5];
    float ax = c[3*i+6] - ox, ay = c[3*i+7] - oy, az = c[3*i+8] - oz;
    float i1 = rsqrt_fast(ax*ax + ay*ay + az*az);
    ax *= i1; ay *= i1; az *= i1;
    float bx = c[3*i] - ox, by = c[3*i+1] - oy, bz = c[3*i+2] - oz;
    float d = bx*ax + by*ay + bz*az;
    bx -= d*ax; by -= d*ay; bz -= d*az;
    float i2 = rsqrt_fast(bx*bx + by*by + bz*bz);
    bx *= i2; by *= i2; bz *= i2;
    R[0]=ax; R[1]=ay; R[2]=az;
    R[3]=bx; R[4]=by; R[5]=bz;
    R[6]=ay*bz - az*by; R[7]=az*bx - ax*bz; R[8]=ax*by - ay*bx;
    o[0]=ox; o[1]=oy; o[2]=oz;
}

__global__ void prep_kernel(const float* __restrict__ pred, const float* __restrict__ tru) {
    int i = blockIdx.x * blockDim.x + threadIdx.x;
    if (i == 0) g_acc = 0.0;
    if (i < NPTS) {
        g_pd[0][i] = dupf(-pred[3*i]);
        g_pd[1][i] = dupf(-pred[3*i+1]);
        g_pd[2][i] = dupf(-pred[3*i+2]);
        g_pd[3][i] = dupf(tru[3*i]);
        g_pd[4][i] = dupf(tru[3*i+1]);
        g_pd[5][i] = dupf(tru[3*i+2]);
    }
    if (i < NF) {
        float Rp[9], op[3], Rt[9], ot[3];
        build_frame(pred, i, Rp, op);
        build_frame(tru,  i, Rt, ot);
        float M[9];
        #pragma unroll
        for (int r = 0; r < 3; r++)
            #pragma unroll
            for (int cc = 0; cc < 3; cc++)
                M[3*r+cc] = Rp[r]*Rt[cc] + Rp[3+r]*Rt[3+cc] + Rp[6+r]*Rt[6+cc];
        #pragma unroll
        for (int k = 0; k < 9; k++) g_fc[k][i] = M[k];
        #pragma unroll
        for (int r = 0; r < 3; r++)
            g_fc[9 + r][i] = op[r] - (M[3*r]*ot[0] + M[3*r+1]*ot[1] + M[3*r+2]*ot[2]);
    } else if (i < NPTS) {
        // Pad frames: dist clamps to exactly 10.0; removed analytically at the end.
        #pragma unroll
        for (int k = 0; k < 12; k++) g_fc[k][i] = 0.0f;
        g_fc[9][i] = 1e6f;
    }
}

// Each block: 4 frames (two f32x2 frame-pairs) x 2048 points.
__global__ void __launch_bounds__(LT, 3) loss_kernel(float* __restrict__ out) {
    const int f  = (blockIdx.x >> 1) * 4;
    const int n0 = (blockIdx.x & 1) * PT_CHUNK;

    const float* __restrict__ fc = &g_fc[0][f];
    u64 A[12], B[12];
    #pragma unroll
    for (int k = 0; k < 12; k++) {
        A[k] = *(const u64*)(fc + k * NPTS);
        B[k] = *(const u64*)(fc + k * NPTS + 2);
    }
    const u64 eps2 = dupf(EPSF);

    float s0 = 0.0f, s1 = 0.0f, s2 = 0.0f, s3 = 0.0f;

    const u64* __restrict__ pt = &g_pd[0][n0 + threadIdx.x];

    #pragma unroll
    for (int it = 0; it < PT_CHUNK / LT; it += 2, pt += 2 * LT) {
        // Batch all 12 loads up front: pure LDG.64, no marshalling, MLP=12.
        u64 NX0 = pt[0*NPTS],      NY0 = pt[1*NPTS],      NZ0 = pt[2*NPTS];
        u64 U0  = pt[3*NPTS],      V0  = pt[4*NPTS],      W0  = pt[5*NPTS];
        u64 NX1 = pt[0*NPTS + LT], NY1 = pt[1*NPTS + LT], NZ1 = pt[2*NPTS + LT];
        u64 U1  = pt[3*NPTS + LT], V1  = pt[4*NPTS + LT], W1  = pt[5*NPTS + LT];

        // d = M*q + c - p  (sign of d irrelevant for |d|^2)
        u64 ax0 = ffma2(A[0], U0, ffma2(A[1], V0, ffma2(A[2], W0, fadd2(A[9],  NX0))));
        u64 ay0 = ffma2(A[3], U0, ffma2(A[4], V0, ffma2(A[5], W0, fadd2(A[10], NY0))));
        u64 az0 = ffma2(A[6], U0, ffma2(A[7], V0, ffma2(A[8], W0, fadd2(A[11], NZ0))));
        u64 bx0 = ffma2(B[0], U0, ffma2(B[1], V0, ffma2(B[2], W0, fadd2(B[9],  NX0))));
        u64 by0 = ffma2(B[3], U0, ffma2(B[4], V0, ffma2(B[5], W0, fadd2(B[10], NY0))));
        u64 bz0 = ffma2(B[6], U0, ffma2(B[7], V0, ffma2(B[8], W0, fadd2(B[11], NZ0))));

        u64 ax1 = ffma2(A[0], U1, ffma2(A[1], V1, ffma2(A[2], W1, fadd2(A[9],  NX1))));
        u64 ay1 = ffma2(A[3], U1, ffma2(A[4], V1, ffma2(A[5], W1, fadd2(A[10], NY1))));
        u64 az1 = ffma2(A[6], U1, ffma2(A[7], V1, ffma2(A[8], W1, fadd2(A[11], NZ1))));
        u64 bx1 = ffma2(B[0], U1, ffma2(B[1], V1, ffma2(B[2], W1, fadd2(B[9],  NX1))));
        u64 by1 = ffma2(B[3], U1, ffma2(B[4], V1, ffma2(B[5], W1, fadd2(B[10], NY1))));
        u64 bz1 = ffma2(B[6], U1, ffma2(B[7], V1, ffma2(B[8], W1, fadd2(B[11], NZ1))));

        u64 ssa0 = ffma2(ax0, ax0, ffma2(ay0, ay0, ffma2(az0, az0, eps2)));
        u64 ssb0 = ffma2(bx0, bx0, ffma2(by0, by0, ffma2(bz0, bz0, eps2)));
        u64 ssa1 = ffma2(ax1, ax1, ffma2(ay1, ay1, ffma2(az1, az1, eps2)));
        u64 ssb1 = ffma2(bx1, bx1, ffma2(by1, by1, ffma2(bz1, bz1, eps2)));

        float v0, v1, v2, v3, v4, v5, v6, v7;
        unpk(ssa0, v0, v1);
        unpk(ssb0, v2, v3);
        unpk(ssa1, v4, v5);
        unpk(ssb1, v6, v7);
        s0 += fminf(sqrt_fast(v0), 10.0f);
        s1 += fminf(sqrt_fast(v1), 10.0f);
        s2 += fminf(sqrt_fast(v2), 10.0f);
        s3 += fminf(sqrt_fast(v3), 10.0f);
        s0 += fminf(sqrt_fast(v4), 10.0f);
        s1 += fminf(sqrt_fast(v5), 10.0f);
        s2 += fminf(sqrt_fast(v6), 10.0f);
        s3 += fminf(sqrt_fast(v7), 10.0f);
    }

    float sum = (s0 + s1) + (s2 + s3);
    #pragma unroll
    for (int o = 16; o > 0; o >>= 1)
        sum += __shfl_down_sync(0xffffffffu, sum, o);

    __shared__ float wsum[LT / 32];
    int lane = threadIdx.x & 31;
    int wid  = threadIdx.x >> 5;
    if (lane == 0) wsum[wid] = sum;
    __syncthreads();
    if (threadIdx.x == 0) {
        float v = 0.0f;
        #pragma unroll
        for (int w = 0; w < LT / 32; w++) v += wsum[w];
        atomicAdd(&g_acc, (double)v);
        __threadfence();
        unsigned t = atomicAdd(&g_tick, 1u);
        if (t == (unsigned)(gridDim.x - 1)) {
            double total = *((volatile double*)&g_acc);
            total -= 2.0 * (double)NPTS * 10.0;   // pad frames contribute exactly 10 each
            out[0] = (float)(total / ((double)NF * (double)NPTS) / 10.0);
            g_tick = 0u;  // reset for next graph replay
        }
    }
}

extern "C" void kernel_launch(void* const* d_in, const int* in_sizes, int n_in,
                              void* d_out, int out_size) {
    const float* pred = (const float*)d_in[0];
    const float* tru  = (const float*)d_in[1];
    float* out = (float*)d_out;

    prep_kernel<<<(NPTS + 255) / 256, 256>>>(pred, tru);
    loss_kernel<<<NBLK, LT>>>(out);
}